// round 11
// baseline (speedup 1.0000x reference)
#include <cuda_runtime.h>

// SKA_Small: out[b,g,cg,h,w] = sum_{3x3 taps} x[b,g,cg,h+ki-1,w+kj-1] * w[b,g,ki*3+kj,h,w]
// x: [8,64,128,128] f32, w: [8,8,1,9,128,128] f32, out like x.
//
// R8: R6's per-item code (warp = (bg,h) row, all 8 channels, w read once
// chip-wide, shfl halos) + persistent blocks with atomic work-stealing.
// 592 blocks = exactly 4/SM on all 148 SMs; warps grab chunks of 4
// consecutive rows -> perfect SM load balance + halo-row L1 reuse in-warp.

constexpr int B = 8, C = 64, H = 128, W = 128, G = 8, CG = 8;
constexpr int HW = H * W;
constexpr int ITEMS = (B * G) * H;   // 8192 (bg, h) rows
constexpr int CHUNK = 4;

__device__ unsigned int g_ctr;

__global__ void reset_ctr_kernel() { g_ctr = 0u; }

__global__ __launch_bounds__(256, 4) void ska_small_kernel(
    const float* __restrict__ x,
    const float* __restrict__ w,
    float* __restrict__ out)
{
    const int lane = threadIdx.x & 31;
    const int w0   = lane * 4;

    for (;;) {
        unsigned int base;
        if (lane == 0) base = atomicAdd(&g_ctr, (unsigned int)CHUNK);
        base = __shfl_sync(0xffffffffu, base, 0);
        if (base >= (unsigned int)ITEMS) break;

        #pragma unroll 1
        for (int i = 0; i < CHUNK; i++) {
            const int item = (int)base + i;      // ITEMS % CHUNK == 0
            const int h    = item & 127;
            const int bg   = item >> 7;          // b*G + g

            // ---- 9 per-pixel weight vectors, resident across all 8 channels ----
            const float* wbp = w + (bg * 9) * HW + h * W + w0;
            float4 wk[9];
            #pragma unroll
            for (int k = 0; k < 9; k++)
                wk[k] = *(const float4*)(wbp + k * HW);

            const bool hm = (h > 0);
            const bool hp = (h < H - 1);

            const float* xb = x   + (bg * CG) * HW + h * W + w0;
            float*       ob = out + (bg * CG) * HW + h * W + w0;

            #pragma unroll
            for (int c = 0; c < CG; c++) {
                const float* xch = xb + c * HW;

                float4 v0 = hm ? *(const float4*)(xch - W) : make_float4(0.f, 0.f, 0.f, 0.f);
                float4 v1 =      *(const float4*)(xch);
                float4 v2 = hp ? *(const float4*)(xch + W) : make_float4(0.f, 0.f, 0.f, 0.f);

                float a0 = 0.f, a1 = 0.f, a2 = 0.f, a3 = 0.f;

                #pragma unroll
                for (int ki = 0; ki < 3; ki++) {
                    const float4 v = (ki == 0) ? v0 : (ki == 1) ? v1 : v2;
                    float l = __shfl_up_sync(0xffffffffu, v.w, 1);
                    float r = __shfl_down_sync(0xffffffffu, v.x, 1);
                    if (lane == 0)  l = 0.f;
                    if (lane == 31) r = 0.f;

                    const float4 wa = wk[ki * 3 + 0];  // tap (ki,0): x[w-1]
                    const float4 wm = wk[ki * 3 + 1];  // tap (ki,1): x[w]
                    const float4 wc = wk[ki * 3 + 2];  // tap (ki,2): x[w+1]

                    a0 = fmaf(wa.x, l,   fmaf(wm.x, v.x, fmaf(wc.x, v.y, a0)));
                    a1 = fmaf(wa.y, v.x, fmaf(wm.y, v.y, fmaf(wc.y, v.z, a1)));
                    a2 = fmaf(wa.z, v.y, fmaf(wm.z, v.z, fmaf(wc.z, v.w, a2)));
                    a3 = fmaf(wa.w, v.z, fmaf(wm.w, v.w, fmaf(wc.w, r,   a3)));
                }

                *(float4*)(ob + c * HW) = make_float4(a0, a1, a2, a3);
            }
        }
    }
}

extern "C" void kernel_launch(void* const* d_in, const int* in_sizes, int n_in,
                              void* d_out, int out_size)
{
    const float* x = (const float*)d_in[0];
    const float* w = (const float*)d_in[1];
    float* out = (float*)d_out;

    reset_ctr_kernel<<<1, 1>>>();
    // 592 blocks = 148 SMs x 4 blocks (64 regs x 256 thr x 4 = full RF)
    ska_small_kernel<<<592, 256>>>(x, w, out);
}

// round 13
// speedup vs baseline: 1.7166x; 1.7166x over previous
#include <cuda_runtime.h>

// SKA_Small: out[b,g,cg,h,w] = sum_{3x3 taps} x[b,g,cg,h+ki-1,w+kj-1] * w[b,g,ki*3+kj,h,w]
// x: [8,64,128,128] f32, w: [8,8,1,9,128,128] f32, out like x.
//
// R9 = R6 (best, 19.2us) + two latency tweaks:
//  - warp's 2 items are CONSECUTIVE rows (2k, 2k+1) of one bg: item-2's x
//    rows were just loaded by item-1 in the same warp -> L1 hits (~39 cyc
//    instead of ~250 cyc warm-L2).
//  - out written with __stcs (streaming): keeps x+w L2-resident across graph
//    replays instead of letting write-once out evict them.

constexpr int B = 8, C = 64, H = 128, W = 128, G = 8, CG = 8;
constexpr int HW = H * W;
constexpr int ITEMS = (B * G) * H;   // 8192 warp-rows
constexpr int WARPS = ITEMS / 2;     // 4096 resident warps

__global__ __launch_bounds__(256, 4) void ska_small_kernel(
    const float* __restrict__ x,
    const float* __restrict__ w,
    float* __restrict__ out)
{
    const int lane  = threadIdx.x & 31;
    const int warp0 = (blockIdx.x * 256 + threadIdx.x) >> 5;  // 0..4095
    const int w0    = lane * 4;

    #pragma unroll
    for (int it = 0; it < 2; it++) {
        const int item = warp0 * 2 + it;       // consecutive rows per warp
        const int h    = item & 127;
        const int bg   = item >> 7;            // b*G + g

        // ---- 9 per-pixel weight vectors, resident across all 8 channels ----
        const float* wbp = w + (bg * 9) * HW + h * W + w0;
        float4 wk[9];
        #pragma unroll
        for (int k = 0; k < 9; k++)
            wk[k] = *(const float4*)(wbp + k * HW);

        const bool hm = (h > 0);
        const bool hp = (h < H - 1);

        const float* xb = x   + (bg * CG) * HW + h * W + w0;
        float*       ob = out + (bg * CG) * HW + h * W + w0;

        #pragma unroll
        for (int c = 0; c < CG; c++) {
            const float* xch = xb + c * HW;

            float4 v0 = hm ? *(const float4*)(xch - W) : make_float4(0.f, 0.f, 0.f, 0.f);
            float4 v1 =      *(const float4*)(xch);
            float4 v2 = hp ? *(const float4*)(xch + W) : make_float4(0.f, 0.f, 0.f, 0.f);

            float a0 = 0.f, a1 = 0.f, a2 = 0.f, a3 = 0.f;

            #pragma unroll
            for (int ki = 0; ki < 3; ki++) {
                const float4 v = (ki == 0) ? v0 : (ki == 1) ? v1 : v2;
                float l = __shfl_up_sync(0xffffffffu, v.w, 1);
                float r = __shfl_down_sync(0xffffffffu, v.x, 1);
                if (lane == 0)  l = 0.f;
                if (lane == 31) r = 0.f;

                const float4 wa = wk[ki * 3 + 0];  // tap (ki,0): x[w-1]
                const float4 wm = wk[ki * 3 + 1];  // tap (ki,1): x[w]
                const float4 wc = wk[ki * 3 + 2];  // tap (ki,2): x[w+1]

                a0 = fmaf(wa.x, l,   fmaf(wm.x, v.x, fmaf(wc.x, v.y, a0)));
                a1 = fmaf(wa.y, v.x, fmaf(wm.y, v.y, fmaf(wc.y, v.z, a1)));
                a2 = fmaf(wa.z, v.y, fmaf(wm.z, v.z, fmaf(wc.z, v.w, a2)));
                a3 = fmaf(wa.w, v.z, fmaf(wm.w, v.w, fmaf(wc.w, r,   a3)));
            }

            __stcs((float4*)(ob + c * HW), make_float4(a0, a1, a2, a3));
        }
    }
}

extern "C" void kernel_launch(void* const* d_in, const int* in_sizes, int n_in,
                              void* d_out, int out_size)
{
    const float* x = (const float*)d_in[0];
    const float* w = (const float*)d_in[1];
    float* out = (float*)d_out;

    // 4096 warps = 512 blocks x 256 threads; 4 blocks/SM -> single wave
    ska_small_kernel<<<WARPS * 32 / 256, 256>>>(x, w, out);
}